// round 1
// baseline (speedup 1.0000x reference)
#include <cuda_runtime.h>
#include <stdint.h>
#include <limits.h>

#define H 64
#define ROWS_PER_BLOCK 4
#define MAXB 16384

// scratch (no device allocation allowed)
__device__ float g_row_loss[MAXB];
__device__ float g_row_has[MAXB];

__global__ void __launch_bounds__(256) pairloss_row_kernel(
    const float* __restrict__ scores,
    const int* __restrict__ rankings,
    const uint8_t* __restrict__ mask,
    int B)
{
    __shared__ float s_s[ROWS_PER_BLOCK][H];
    __shared__ int   s_r[ROWS_PER_BLOCK][H];
    __shared__ float s_part[ROWS_PER_BLOCK][2];
    __shared__ int   s_cnt[ROWS_PER_BLOCK][2];

    const int tid = threadIdx.x;
    const int g   = tid >> 6;     // row group within block (0..3)
    const int i   = tid & 63;     // horse index within row
    const int row = blockIdx.x * ROWS_PER_BLOCK + g;

    float si = 0.0f;
    int   ri = INT_MIN;
    if (row < B) {
        const int idx = row * H + i;
        si = scores[idx];
        const int r = rankings[idx];
        const bool v = (mask[idx] != 0) && (r > 0);
        ri = v ? r : INT_MIN;     // invalid -> never satisfies ri < rj or r_i-valid check
    }
    s_s[g][i] = si;
    s_r[g][i] = ri;
    __syncthreads();

    float acc = 0.0f;
    int   cnt = 0;
    if (ri != INT_MIN) {
        #pragma unroll
        for (int j = 0; j < H; ++j) {
            const int rj = s_r[g][j];        // broadcast within group slice
            if (ri < rj) {                   // rj==INT_MIN never passes
                const float h = 1.0f - (si - s_s[g][j]);
                acc += fmaxf(h, 0.0f);
                ++cnt;
            }
        }
    }

    // warp-level reduce (each 64-thread group = 2 warps)
    #pragma unroll
    for (int off = 16; off > 0; off >>= 1) {
        acc += __shfl_down_sync(0xffffffffu, acc, off);
        cnt += __shfl_down_sync(0xffffffffu, cnt, off);
    }
    const int warp_in_g = (i >> 5);
    if ((i & 31) == 0) {
        s_part[g][warp_in_g] = acc;
        s_cnt[g][warp_in_g]  = cnt;
    }
    __syncthreads();

    if (i == 0 && row < B) {
        const float total = s_part[g][0] + s_part[g][1];
        const int   c     = s_cnt[g][0] + s_cnt[g][1];
        g_row_loss[row] = (c > 0) ? (total / (float)c) : 0.0f;
        g_row_has[row]  = (c > 0) ? 1.0f : 0.0f;
    }
}

__global__ void __launch_bounds__(256) pairloss_reduce_kernel(float* __restrict__ out, int B)
{
    __shared__ float s_l[256];
    __shared__ float s_h[256];
    const int tid = threadIdx.x;

    float l = 0.0f, h = 0.0f;
    for (int r = tid; r < B; r += 256) {
        l += g_row_loss[r];
        h += g_row_has[r];
    }
    s_l[tid] = l;
    s_h[tid] = h;
    __syncthreads();

    #pragma unroll
    for (int s = 128; s > 0; s >>= 1) {
        if (tid < s) {
            s_l[tid] += s_l[tid + s];
            s_h[tid] += s_h[tid + s];
        }
        __syncthreads();
    }

    if (tid == 0) {
        const float n = s_h[0];
        out[0] = (n > 0.0f) ? (s_l[0] / n) : 0.0f;
    }
}

extern "C" void kernel_launch(void* const* d_in, const int* in_sizes, int n_in,
                              void* d_out, int out_size)
{
    const float*   scores   = (const float*)d_in[0];
    const int*     rankings = (const int*)d_in[1];
    const uint8_t* mask     = (const uint8_t*)d_in[2];
    float*         out      = (float*)d_out;

    const int B = in_sizes[0] / H;
    const int nblocks = (B + ROWS_PER_BLOCK - 1) / ROWS_PER_BLOCK;

    pairloss_row_kernel<<<nblocks, 256>>>(scores, rankings, mask, B);
    pairloss_reduce_kernel<<<1, 256>>>(out, B);
}

// round 5
// speedup vs baseline: 1.4090x; 1.4090x over previous
#include <cuda_runtime.h>
#include <stdint.h>
#include <math.h>

#define H 64
#define RPB 8                 // rows per block, one warp per row
#define THREADS (RPB * 32)
#define MAXPART 8192

__device__ float2 g_part[MAXPART];

__global__ void __launch_bounds__(THREADS) pairloss_row_kernel(
    const float* __restrict__ scores,
    const int* __restrict__ rankings,
    const uint8_t* __restrict__ mask,
    int B)
{
    // per row: entries 0..63 = elements, 64..95 = duplicate of elements 0..31
    __shared__ float2 sh[RPB][96];
    __shared__ float2 sh_row[RPB];

    const int lane = threadIdx.x & 31;
    const int w    = threadIdx.x >> 5;
    const int row  = blockIdx.x * RPB + w;

    const float NaNf = __int_as_float(0x7fffffff);

    float s0 = 0.f, s1 = 0.f, fr0 = NaNf, fr1 = NaNf;
    if (row < B) {
        const int base = row * H + lane;
        s0 = scores[base];
        s1 = scores[base + 32];
        const int r0 = rankings[base];
        const int r1 = rankings[base + 32];
        const bool v0 = (mask[base] != 0) && (r0 > 0);
        const bool v1 = (mask[base + 32] != 0) && (r1 > 0);
        fr0 = v0 ? (float)r0 : NaNf;    // invalid -> NaN: all its pairs drop out
        fr1 = v1 ? (float)r1 : NaNf;
    }
    sh[w][lane]      = make_float2(fr0, s0);
    sh[w][lane + 32] = make_float2(fr1, s1);
    sh[w][lane + 64] = make_float2(fr0, s0);   // duplicate for wrap-free indexing
    __syncwarp();

    float acc0 = 0.f, cnt0 = 0.f, acc1 = 0.f, cnt1 = 0.f;

    // held pair (lane, lane+32): circular distance 32, each such pair owned by one thread
    {
        const float dr = fr1 - fr0;
        const float sg = __int_as_float((__float_as_int(dr) & 0x80000000u) | 0x3f800000u);
        const float t  = fmaxf(fmaf(s0 - s1, -sg, 1.0f), 0.0f);
        if (fabsf(dr) >= 1.0f) { acc0 += t; cnt0 += 1.0f; }   // NaN/tie -> false
    }

    const float2* rowsh = sh[w];
    #pragma unroll
    for (int k = 1; k <= 31; ++k) {
        const float2 q0 = rowsh[lane + k];        // element (lane+k)      (< 63, no wrap)
        const float2 q1 = rowsh[lane + 32 + k];   // element (lane+32+k) mod 64 via duplicate
        // unordered pair {lane, lane+k}
        {
            const float dr = q0.x - fr0;          // rank_j - rank_i
            const float sg = __int_as_float((__float_as_int(dr) & 0x80000000u) | 0x3f800000u);
            const float t  = fmaxf(fmaf(s0 - q0.y, -sg, 1.0f), 0.0f);
            if (fabsf(dr) >= 1.0f) { acc0 += t; cnt0 += 1.0f; }
        }
        // unordered pair {lane+32, (lane+32+k) mod 64}
        {
            const float dr = q1.x - fr1;
            const float sg = __int_as_float((__float_as_int(dr) & 0x80000000u) | 0x3f800000u);
            const float t  = fmaxf(fmaf(s1 - q1.y, -sg, 1.0f), 0.0f);
            if (fabsf(dr) >= 1.0f) { acc1 += t; cnt1 += 1.0f; }
        }
    }

    float acc = acc0 + acc1;
    float cnt = cnt0 + cnt1;
    #pragma unroll
    for (int o = 16; o > 0; o >>= 1) {
        acc += __shfl_down_sync(0xffffffffu, acc, o);
        cnt += __shfl_down_sync(0xffffffffu, cnt, o);
    }
    if (lane == 0) {
        const float loss = (cnt > 0.f) ? (acc / cnt) : 0.f;
        sh_row[w] = make_float2(loss, (cnt > 0.f) ? 1.f : 0.f);
    }
    __syncthreads();

    if (threadIdx.x == 0) {
        float l = 0.f, h = 0.f;
        #pragma unroll
        for (int i = 0; i < RPB; ++i) { l += sh_row[i].x; h += sh_row[i].y; }
        g_part[blockIdx.x] = make_float2(l, h);
    }
}

__global__ void __launch_bounds__(256) pairloss_final_kernel(float* __restrict__ out, int nparts)
{
    __shared__ float s_l[256];
    __shared__ float s_h[256];
    const int tid = threadIdx.x;

    float l = 0.f, h = 0.f;
    for (int i = tid; i < nparts; i += 256) {
        const float2 p = g_part[i];
        l += p.x;
        h += p.y;
    }
    s_l[tid] = l;
    s_h[tid] = h;
    __syncthreads();

    #pragma unroll
    for (int s = 128; s > 0; s >>= 1) {
        if (tid < s) {
            s_l[tid] += s_l[tid + s];
            s_h[tid] += s_h[tid + s];
        }
        __syncthreads();
    }

    if (tid == 0) {
        const float n = s_h[0];
        out[0] = (n > 0.f) ? (s_l[0] / n) : 0.f;
    }
}

extern "C" void kernel_launch(void* const* d_in, const int* in_sizes, int n_in,
                              void* d_out, int out_size)
{
    const float*   scores   = (const float*)d_in[0];
    const int*     rankings = (const int*)d_in[1];
    const uint8_t* mask     = (const uint8_t*)d_in[2];
    float*         out      = (float*)d_out;

    const int B = in_sizes[0] / H;
    const int nblocks = (B + RPB - 1) / RPB;

    pairloss_row_kernel<<<nblocks, THREADS>>>(scores, rankings, mask, B);
    pairloss_final_kernel<<<1, 256>>>(out, nblocks);
}